// round 2
// baseline (speedup 1.0000x reference)
#include <cuda_runtime.h>
#include <cuda_bf16.h>
#include <cstdint>

#define H 128
#define MAXN 50000
#define NBUF ((size_t)MAXN * H)
#define EPW 4
#define EDGE_WARPS 8
#define EDGE_BLOCK 256
#define EDGE_SMEM (128*128*4 + EDGE_WARPS*EPW*128*4)   // 64KB W2 + 16KB h staging

// Scratch: X1, X2 (ping-pong node features), A, B (per-node partial GEMMs)
// float4-typed => guaranteed 16B alignment for vector loads.
__device__ float4 g_scratch4[4 * NBUF / 4];

__device__ __forceinline__ void atomicMaxF(float* addr, float v) {
    // Correct for mixed signs: positives via signed max, negatives via unsigned min.
    if (v >= 0.f) atomicMax((int*)addr, __float_as_int(v));
    else          atomicMin((unsigned int*)addr, __float_as_uint(v));
}

// ---------------------------------------------------------------------------
// Node GEMM: A[n] = x[n] @ (W1a - W1b) + b1 ;  B[n] = x[n] @ W1b
// W1l layout: [2H][H] row-major (rows 0..H-1 = W1a, rows H..2H-1 = W1b)
// Block: 128 threads (one per output column), 32 nodes per block.
// ---------------------------------------------------------------------------
__global__ void __launch_bounds__(128) node_gemm_kernel(
    const float* __restrict__ x, const float* __restrict__ W1l,
    const float* __restrict__ b1l, float* __restrict__ A, float* __restrict__ Bm,
    int nN)
{
    __shared__ float xs[32][H];
    const int c = threadIdx.x;
    const int n0 = blockIdx.x * 32;

    #pragma unroll
    for (int n = 0; n < 32; n++) {
        int node = n0 + n;
        xs[n][c] = (node < nN) ? x[(size_t)node * H + c] : 0.f;
    }
    __syncthreads();

    float accA[32], accB[32];
    const float bias = b1l[c];
    #pragma unroll
    for (int n = 0; n < 32; n++) { accA[n] = bias; accB[n] = 0.f; }

    for (int k = 0; k < H; k++) {
        const float wa = W1l[k * H + c];
        const float wb = W1l[(H + k) * H + c];
        const float wd = wa - wb;
        #pragma unroll
        for (int n = 0; n < 32; n++) {
            const float xv = xs[n][k];
            accA[n] = fmaf(xv, wd, accA[n]);
            accB[n] = fmaf(xv, wb, accB[n]);
        }
    }

    #pragma unroll
    for (int n = 0; n < 32; n++) {
        int node = n0 + n;
        if (node < nN) {
            A [(size_t)node * H + c] = accA[n];
            Bm[(size_t)node * H + c] = accB[n];
        }
    }
}

// ---------------------------------------------------------------------------
// Edge kernel: for each edge e (incl. self loops):
//   h = relu(A[dst] + B[src]);  out = h @ W2 + b2;  y[dst] = max(y[dst], out)
// Warp processes EPW=4 edges at a time (amortizes W2 smem reads 4x).
// Lane owns output columns [4*lane, 4*lane+4) -> all smem traffic is LDS.128,
// conflict-free. Racy read-skip before atomics (safe for max).
// ---------------------------------------------------------------------------
__global__ void __launch_bounds__(EDGE_BLOCK) edge_kernel(
    const float* __restrict__ A, const float* __restrict__ Bm,
    const float* __restrict__ W2, const float* __restrict__ b2,
    const int* __restrict__ ei, float* __restrict__ y,
    int nE, int nN)
{
    extern __shared__ float sm[];
    float* W2s = sm;                               // [128][128]
    const int tid  = threadIdx.x;
    const int lane = tid & 31;
    const int wid  = tid >> 5;
    float* hs = sm + 128 * 128 + wid * (EPW * H);  // per-warp h staging

    for (int i = tid * 4; i < 128 * 128; i += EDGE_BLOCK * 4)
        *(float4*)(W2s + i) = *(const float4*)(W2 + i);
    __syncthreads();

    const float4 b2v = *(const float4*)(b2 + lane * 4);

    const int nwork  = nE + nN;
    const int gw     = blockIdx.x * EDGE_WARPS + wid;
    const int stride = gridDim.x * EDGE_WARPS * EPW;

    for (int base = gw * EPW; base < nwork; base += stride) {
        int sidx[EPW], didx[EPW];
        #pragma unroll
        for (int j = 0; j < EPW; j++) {
            const int e = base + j;
            if (e < nE)         { sidx[j] = ei[e]; didx[j] = ei[nE + e]; }
            else if (e < nwork) { sidx[j] = didx[j] = e - nE; }   // self loop
            else                { sidx[j] = didx[j] = -1; }
        }

        // h = relu(A[dst] + B[src]) -> per-warp smem staging
        #pragma unroll
        for (int j = 0; j < EPW; j++) {
            float4 h = make_float4(0.f, 0.f, 0.f, 0.f);
            if (didx[j] >= 0) {
                const float4 a = *(const float4*)(A  + (size_t)didx[j] * H + lane * 4);
                const float4 b = *(const float4*)(Bm + (size_t)sidx[j] * H + lane * 4);
                h.x = fmaxf(a.x + b.x, 0.f);
                h.y = fmaxf(a.y + b.y, 0.f);
                h.z = fmaxf(a.z + b.z, 0.f);
                h.w = fmaxf(a.w + b.w, 0.f);
            }
            *(float4*)(hs + j * H + lane * 4) = h;
        }
        __syncwarp();

        float4 acc[EPW];
        #pragma unroll
        for (int j = 0; j < EPW; j++) acc[j] = make_float4(0.f, 0.f, 0.f, 0.f);

        #pragma unroll 4
        for (int k = 0; k < H; k += 4) {
            const float4 w0 = *(float4*)(W2s + (k + 0) * H + lane * 4);
            const float4 w1 = *(float4*)(W2s + (k + 1) * H + lane * 4);
            const float4 w2r = *(float4*)(W2s + (k + 2) * H + lane * 4);
            const float4 w3 = *(float4*)(W2s + (k + 3) * H + lane * 4);
            #pragma unroll
            for (int j = 0; j < EPW; j++) {
                const float4 h4 = *(float4*)(hs + j * H + k);   // broadcast
                acc[j].x = fmaf(h4.x, w0.x, fmaf(h4.y, w1.x, fmaf(h4.z, w2r.x, fmaf(h4.w, w3.x, acc[j].x))));
                acc[j].y = fmaf(h4.x, w0.y, fmaf(h4.y, w1.y, fmaf(h4.z, w2r.y, fmaf(h4.w, w3.y, acc[j].y))));
                acc[j].z = fmaf(h4.x, w0.z, fmaf(h4.y, w1.z, fmaf(h4.z, w2r.z, fmaf(h4.w, w3.z, acc[j].z))));
                acc[j].w = fmaf(h4.x, w0.w, fmaf(h4.y, w1.w, fmaf(h4.z, w2r.w, fmaf(h4.w, w3.w, acc[j].w))));
            }
        }
        __syncwarp();   // protect hs before next iteration's writes

        #pragma unroll
        for (int j = 0; j < EPW; j++) {
            if (didx[j] < 0) continue;
            float* yr = y + (size_t)didx[j] * H + lane * 4;
            const float4 cur = *(const float4*)yr;   // racy read: stale -> conservative skip
            const float v0 = acc[j].x + b2v.x;
            const float v1 = acc[j].y + b2v.y;
            const float v2 = acc[j].z + b2v.z;
            const float v3 = acc[j].w + b2v.w;
            if (!(cur.x >= v0)) atomicMaxF(yr + 0, v0);
            if (!(cur.y >= v1)) atomicMaxF(yr + 1, v1);
            if (!(cur.z >= v2)) atomicMaxF(yr + 2, v2);
            if (!(cur.w >= v3)) atomicMaxF(yr + 3, v3);
        }
    }
}

// ---------------------------------------------------------------------------
// Final: out[n] = x[n] @ Wf + bf   (H=128 -> D=3). Warp per node.
// ---------------------------------------------------------------------------
__global__ void __launch_bounds__(256) final_kernel(
    const float* __restrict__ x, const float* __restrict__ Wf,
    const float* __restrict__ bf, float* __restrict__ out, int nN)
{
    __shared__ float Wfs[H * 3];
    const int tid = threadIdx.x;
    for (int i = tid; i < H * 3; i += 256) Wfs[i] = Wf[i];
    __syncthreads();

    const int lane = tid & 31;
    const int node = blockIdx.x * 8 + (tid >> 5);
    if (node >= nN) return;

    const float4 xv = *(const float4*)(x + (size_t)node * H + lane * 4);
    float s0 = 0.f, s1 = 0.f, s2 = 0.f;
    const float xt[4] = {xv.x, xv.y, xv.z, xv.w};
    #pragma unroll
    for (int t = 0; t < 4; t++) {
        const int k = lane * 4 + t;
        s0 = fmaf(xt[t], Wfs[k * 3 + 0], s0);
        s1 = fmaf(xt[t], Wfs[k * 3 + 1], s1);
        s2 = fmaf(xt[t], Wfs[k * 3 + 2], s2);
    }
    #pragma unroll
    for (int off = 16; off > 0; off >>= 1) {
        s0 += __shfl_down_sync(0xFFFFFFFFu, s0, off);
        s1 += __shfl_down_sync(0xFFFFFFFFu, s1, off);
        s2 += __shfl_down_sync(0xFFFFFFFFu, s2, off);
    }
    if (lane == 0) {
        out[(size_t)node * 3 + 0] = s0 + bf[0];
        out[(size_t)node * 3 + 1] = s1 + bf[1];
        out[(size_t)node * 3 + 2] = s2 + bf[2];
    }
}

// ---------------------------------------------------------------------------
extern "C" void kernel_launch(void* const* d_in, const int* in_sizes, int n_in,
                              void* d_out, int out_size)
{
    const float*      x_in = (const float*)d_in[0];
    const int*        ei   = (const int*)d_in[1];     // int32: JAX x64-disabled
    const float*      W1   = (const float*)d_in[2];   // [L, 2H, H]
    const float*      b1   = (const float*)d_in[3];   // [L, H]
    const float*      W2   = (const float*)d_in[4];   // [L, H, H]
    const float*      b2   = (const float*)d_in[5];   // [L, H]
    const float*      Wf   = (const float*)d_in[6];   // [H, 3]
    const float*      bf   = (const float*)d_in[7];   // [3]
    float*            out  = (float*)d_out;

    const int nN = in_sizes[0] / H;          // 50000
    const int nE = in_sizes[1] / 2;          // 800000
    const int L  = in_sizes[3] / H;          // 4

    void* base = nullptr;
    cudaGetSymbolAddress(&base, g_scratch4);
    float* X1 = (float*)base;
    float* X2 = X1 + NBUF;
    float* A  = X1 + 2 * NBUF;
    float* Bm = X1 + 3 * NBUF;

    cudaFuncSetAttribute(edge_kernel, cudaFuncAttributeMaxDynamicSharedMemorySize, EDGE_SMEM);

    const int nodeBlocks = (nN + 31) / 32;
    const int edgeBlocks = 148 * 2;
    float* bufs[2] = {X1, X2};

    const float* cur = x_in;
    for (int l = 0; l < L; l++) {
        node_gemm_kernel<<<nodeBlocks, 128>>>(cur, W1 + (size_t)l * 2 * H * H,
                                              b1 + (size_t)l * H, A, Bm, nN);
        float* y = bufs[l & 1];
        cudaMemsetAsync(y, 0xFF, (size_t)nN * H * sizeof(float), 0);  // NaN init
        edge_kernel<<<edgeBlocks, EDGE_BLOCK, EDGE_SMEM>>>(
            A, Bm, W2 + (size_t)l * H * H, b2 + (size_t)l * H, ei, y, nE, nN);
        cur = y;
    }
    final_kernel<<<(nN + 7) / 8, 256>>>(cur, Wf, bf, out, nN);
}